// round 13
// baseline (speedup 1.0000x reference)
#include <cuda_runtime.h>
#include <cuda_bf16.h>

// MLPAttention: B=4, N=512, KLEN=512, D=64, TAU=4
//   Wq=W1[0::2], Wk=W1[1::2]; hq=Q@Wq+b1; hk=K@Wk
//   res[n,k] = sum_e relu(hq[n,e]+hk[k,e])*W2[e]   (b2 cancels in softmax)
//   packed f32x2 over e-pairs: fadd2 -> scalar FMNMX relu on halves -> ffma2.
//   att = softmax(res/TAU); out = att@V (k-paired LDS.128 att reads)
// Outputs: out (B*N*D) then att (B*N*K).

#define BB 4
#define NN 512
#define KL 512
#define DD 64

typedef unsigned long long ull;

__device__ float  g_hq[BB * NN * DD];          // [row][e]
__device__ float2 g_hkT2[BB * (DD / 2) * KL];  // [b][ep][k] = {hk[2ep][k], hk[2ep+1][k]}

__device__ __forceinline__ ull pk2(float x, float y) {
    ull r; asm("mov.b64 %0, {%1, %2};" : "=l"(r) : "f"(x), "f"(y)); return r;
}
__device__ __forceinline__ float2 up2(ull u) {
    float2 f; asm("mov.b64 {%0, %1}, %2;" : "=f"(f.x), "=f"(f.y) : "l"(u)); return f;
}
__device__ __forceinline__ ull fadd2(ull a, ull b) {
    ull r; asm("add.rn.f32x2 %0, %1, %2;" : "=l"(r) : "l"(a), "l"(b)); return r;
}
__device__ __forceinline__ ull ffma2(ull a, ull b, ull c) {
    ull r; asm("fma.rn.f32x2 %0, %1, %2, %3;" : "=l"(r) : "l"(a), "l"(b), "l"(c)); return r;
}

// ---------- Kernel A: hq (2 outputs/W1-load) + hkT2 e-paired ----------
// blocks [0,256): hq, 8 rows each. [256,384): hkT2.
__global__ __launch_bounds__(256) void kA(const float* __restrict__ Q,
                                          const float* __restrict__ K,
                                          const float* __restrict__ W1,
                                          const float* __restrict__ b1,
                                          float* __restrict__ hq,
                                          float2* __restrict__ hkT2) {
    int t = threadIdx.x;
    int bid = blockIdx.x;
    if (bid < 256) {
        __shared__ float Qs[8 * 64];
        int r0 = bid * 8;
        Qs[t]       = Q[r0 * 64 + t];
        Qs[t + 256] = Q[r0 * 64 + 256 + t];
        __syncthreads();
        int rl = t >> 6, e = t & 63;          // rows rl and rl+4
        float bv = __ldg(&b1[e]);
        float acc0 = bv, acc1 = bv;
#pragma unroll
        for (int d = 0; d < 64; d++) {
            float wv = __ldg(&W1[d * 128 + e]);            // W1[2d][e], 1 LDG / 2 FMA
            acc0 = fmaf(Qs[rl * 64 + d], wv, acc0);
            acc1 = fmaf(Qs[(rl + 4) * 64 + d], wv, acc1);
        }
        hq[(r0 + rl) * 64 + e]     = acc0;
        hq[(r0 + rl + 4) * 64 + e] = acc1;
    } else {
        __shared__ float Ks[64 * 65];
        __shared__ float Ws[64 * 16];   // [d][eq]
        int id = bid - 256;
        int b  = id >> 5;
        int kt = (id >> 2) & 7;
        int qt = id & 3;
#pragma unroll
        for (int j = 0; j < 16; j++) {
            int idx = t + 256 * j;
            int kk = idx >> 6, d = idx & 63;
            Ks[kk * 65 + d] = K[(b * 512 + kt * 64 + kk) * 64 + d];
        }
#pragma unroll
        for (int j = 0; j < 4; j++) {
            int idx = t + 256 * j;
            int d = idx >> 4, eq = idx & 15;
            Ws[idx] = W1[d * 128 + 64 + qt * 16 + eq];   // W1[2d+1][qt*16+eq]
        }
        __syncthreads();
        int k = t & 63, ei = t >> 6;
        float a0 = 0.f, a1 = 0.f, a2 = 0.f, a3 = 0.f;
#pragma unroll
        for (int d = 0; d < 64; d++) {
            float kv = Ks[k * 65 + d];
            float4 wv = *(const float4*)&Ws[d * 16 + ei * 4];
            a0 = fmaf(kv, wv.x, a0);
            a1 = fmaf(kv, wv.y, a1);
            a2 = fmaf(kv, wv.z, a2);
            a3 = fmaf(kv, wv.w, a3);
        }
        int e0 = qt * 16 + ei * 4;
        int base = b * (32 * 512) + kt * 64 + k;
        hkT2[base + (e0 >> 1) * 512]       = make_float2(a0, a1);
        hkT2[base + ((e0 >> 1) + 1) * 512] = make_float2(a2, a3);
    }
}

// ---------- Kernel BC: res -> softmax -> att, out = att@V ----------
// grid 256 (b x 64 n-tiles of 8 rows), 512 threads, 2 blocks/SM.
// S (16KB) lifecycle:
//   res [8][512] floats  ->  att2 ull[4 rowpair][512 k]  ->  red [8 split][512]
__global__ __launch_bounds__(512, 2) void kBC(const float* __restrict__ hq,
                                              const float2* __restrict__ hkT2,
                                              const float* __restrict__ W2,
                                              const float* __restrict__ V,
                                              float* __restrict__ att,
                                              float* __restrict__ out) {
    __shared__ __align__(16) float S[4096];
    __shared__ __align__(16) float hq_p[512];   // [ep][row][par]: ep*16 + row*2 + par
    __shared__ ull w2ps[32];                    // {w2[2ep], w2[2ep+1]}

    int b  = blockIdx.x >> 6;
    int n0 = (blockIdx.x & 63) << 3;
    int t  = threadIdx.x;

    {   // stage hq tile (coalesced read, permuted smem write)
        int row = t >> 6, e = t & 63;
        hq_p[(e >> 1) * 16 + row * 2 + (e & 1)] = hq[(b * 512 + n0 + row) * 64 + e];
    }
    if (t < 32) {
        float2 w = *(const float2*)&W2[2 * t];
        w2ps[t] = pk2(w.x, w.y);
    }
    __syncthreads();

    // ---- phase 1: res[8 rows][k=t], packed over e-pairs ----
    // hq_p[ep] spans 16 floats = 4 ulonglong2: hq22[ep*4 + g] = rows {2g, 2g+1}
    const ull* hkb = (const ull*)(hkT2 + b * (32 * 512) + t);
    const ulonglong2* hq22 = (const ulonglong2*)hq_p;

    ull a0=0, a1=0, a2=0, a3=0, a4=0, a5=0, a6=0, a7=0;
#pragma unroll 8
    for (int ep = 0; ep < 32; ep++) {
        ull hkp = hkb[ep * 512];                 // LDG.64 {hk[2ep], hk[2ep+1]}, L2-hot
        ull w2p = w2ps[ep];
        ulonglong2 h01 = hq22[ep * 4];           // rows 0,1
        ulonglong2 h23 = hq22[ep * 4 + 1];       // rows 2,3
        ulonglong2 h45 = hq22[ep * 4 + 2];       // rows 4,5
        ulonglong2 h67 = hq22[ep * 4 + 3];       // rows 6,7
        // RSTEP: fadd2 (fma) -> 2x FMNMX relu (alu) -> ffma2 (fma). 4 slots / 2 MACs.
#define RSTEP(A, H) { float2 s2 = up2(fadd2((H), hkp)); \
                      (A) = ffma2(pk2(fmaxf(s2.x, 0.f), fmaxf(s2.y, 0.f)), w2p, (A)); }
        RSTEP(a0, h01.x) RSTEP(a1, h01.y)
        RSTEP(a2, h23.x) RSTEP(a3, h23.y)
        RSTEP(a4, h45.x) RSTEP(a5, h45.y)
        RSTEP(a6, h67.x) RSTEP(a7, h67.y)
#undef RSTEP
    }
    {   // horizontal add (even-e + odd-e), stage res[8][512]
        float2 x;
        x = up2(a0); S[0 * 512 + t] = x.x + x.y;
        x = up2(a1); S[1 * 512 + t] = x.x + x.y;
        x = up2(a2); S[2 * 512 + t] = x.x + x.y;
        x = up2(a3); S[3 * 512 + t] = x.x + x.y;
        x = up2(a4); S[4 * 512 + t] = x.x + x.y;
        x = up2(a5); S[5 * 512 + t] = x.x + x.y;
        x = up2(a6); S[6 * 512 + t] = x.x + x.y;
        x = up2(a7); S[7 * 512 + t] = x.x + x.y;
    }
    __syncthreads();

    // ---- phase 2: softmax, 16 warps = 2 per row; lane owns 4 consecutive k ----
    int w = t >> 5, lane = t & 31;
    int srow = w >> 1, half = w & 1;
    float* pm = hq_p;          // hq_p free now
    float* ps = hq_p + 16;
    const float* rs = S + srow * 512 + half * 256 + lane * 4;
    float4 va0 = *(const float4*)rs;             // k = base..base+3
    float4 va1 = *(const float4*)(rs + 128);     // k = base+128..+131
    float m = fmaxf(fmaxf(fmaxf(va0.x, va0.y), fmaxf(va0.z, va0.w)),
                    fmaxf(fmaxf(va1.x, va1.y), fmaxf(va1.z, va1.w)));
#pragma unroll
    for (int o = 16; o; o >>= 1) m = fmaxf(m, __shfl_xor_sync(0xffffffffu, m, o));
    va0.x = __expf((va0.x - m) * 0.25f);  va0.y = __expf((va0.y - m) * 0.25f);
    va0.z = __expf((va0.z - m) * 0.25f);  va0.w = __expf((va0.w - m) * 0.25f);
    va1.x = __expf((va1.x - m) * 0.25f);  va1.y = __expf((va1.y - m) * 0.25f);
    va1.z = __expf((va1.z - m) * 0.25f);  va1.w = __expf((va1.w - m) * 0.25f);
    float sum = va0.x + va0.y + va0.z + va0.w + va1.x + va1.y + va1.z + va1.w;
#pragma unroll
    for (int o = 16; o; o >>= 1) sum += __shfl_xor_sync(0xffffffffu, sum, o);
    if (lane == 0) { pm[w] = m; ps[w] = sum; }
    __syncthreads();   // publishes pm/ps; closes all res reads

    float scale;
    {
        float m_o = pm[w ^ 1], s_o = ps[w ^ 1];
        float M = fmaxf(m, m_o);
        float f = __expf((m - M) * 0.25f);
        float sum_t = sum * f + s_o * __expf((m_o - M) * 0.25f);
        scale = f / sum_t;
    }
    va0.x *= scale; va0.y *= scale; va0.z *= scale; va0.w *= scale;
    va1.x *= scale; va1.y *= scale; va1.z *= scale; va1.w *= scale;
    {   // att gmem (STG.128 x2) + att2 smem: float idx r2*1024 + 2k + par
        float* ap = att + (b * 512 + n0 + srow) * 512 + half * 256 + lane * 4;
        *(float4*)ap         = va0;
        *(float4*)(ap + 128) = va1;
        int base = (srow >> 1) * 1024 + (srow & 1) + 2 * (half * 256 + lane * 4);
        S[base]     = va0.x;  S[base + 2] = va0.y;
        S[base + 4] = va0.z;  S[base + 6] = va0.w;
        S[base + 256] = va1.x;  S[base + 258] = va1.y;
        S[base + 260] = va1.z;  S[base + 262] = va1.w;
    }
    __syncthreads();

    // ---- phase 3: out = att @ V. 16 warps = 16 k-splits of 32 (16 k-pairs).
    // att read as ulonglong2 (2 k per LDS.128); V loaded once per block.
    int s = w, d2 = lane;
    const float2* Vb = (const float2*)V + ((size_t)(b * 512) + s * 32) * 32 + d2;
    const ulonglong2* A22 = (const ulonglong2*)S;   // [r2][256 kp]
    ull o0=0, o1=0, o2=0, o3=0, o4=0, o5=0, o6=0, o7=0;  // [r2]x{vx,vy}
#pragma unroll
    for (int i = 0; i < 16; i++) {
        int kp = s * 16 + i;
        float2 v0 = __ldg(Vb + (2 * i) * 32);        // V[k=2kp][2d2..2d2+1]
        float2 v1 = __ldg(Vb + (2 * i + 1) * 32);    // V[k=2kp+1]
        ull vx0 = pk2(v0.x, v0.x), vy0 = pk2(v0.y, v0.y);
        ull vx1 = pk2(v1.x, v1.x), vy1 = pk2(v1.y, v1.y);
        ulonglong2 q0 = A22[kp];                     // rows {0,1}, k = 2kp, 2kp+1
        ulonglong2 q1 = A22[256 + kp];               // rows {2,3}
        ulonglong2 q2 = A22[512 + kp];               // rows {4,5}
        ulonglong2 q3 = A22[768 + kp];               // rows {6,7}
        o0 = ffma2(q0.x, vx0, o0);  o0 = ffma2(q0.y, vx1, o0);
        o1 = ffma2(q0.x, vy0, o1);  o1 = ffma2(q0.y, vy1, o1);
        o2 = ffma2(q1.x, vx0, o2);  o2 = ffma2(q1.y, vx1, o2);
        o3 = ffma2(q1.x, vy0, o3);  o3 = ffma2(q1.y, vy1, o3);
        o4 = ffma2(q2.x, vx0, o4);  o4 = ffma2(q2.y, vx1, o4);
        o5 = ffma2(q2.x, vy0, o5);  o5 = ffma2(q2.y, vy1, o5);
        o6 = ffma2(q3.x, vx0, o6);  o6 = ffma2(q3.y, vx1, o6);
        o7 = ffma2(q3.x, vy0, o7);  o7 = ffma2(q3.y, vy1, o7);
    }
    __syncthreads();   // att2 reads done -> S becomes red[8][512]

    // 2-pass split reduction: splits 0..7 write, splits 8..15 accumulate.
    float* red = S;
    if (s < 8) {
#pragma unroll
        for (int r2 = 0; r2 < 4; r2++) {
            float2 c0 = up2(r2 == 0 ? o0 : r2 == 1 ? o2 : r2 == 2 ? o4 : o6);
            float2 c1 = up2(r2 == 0 ? o1 : r2 == 1 ? o3 : r2 == 2 ? o5 : o7);
            *(float2*)&red[s * 512 + (2 * r2) * 64 + 2 * d2]     = make_float2(c0.x, c1.x);
            *(float2*)&red[s * 512 + (2 * r2 + 1) * 64 + 2 * d2] = make_float2(c0.y, c1.y);
        }
    }
    __syncthreads();
    if (s >= 8) {
#pragma unroll
        for (int r2 = 0; r2 < 4; r2++) {
            float2 c0 = up2(r2 == 0 ? o0 : r2 == 1 ? o2 : r2 == 2 ? o4 : o6);
            float2 c1 = up2(r2 == 0 ? o1 : r2 == 1 ? o3 : r2 == 2 ? o5 : o7);
            float2* p0 = (float2*)&red[(s - 8) * 512 + (2 * r2) * 64 + 2 * d2];
            float2* p1 = (float2*)&red[(s - 8) * 512 + (2 * r2 + 1) * 64 + 2 * d2];
            float2 q0 = *p0, q1 = *p1;
            *p0 = make_float2(q0.x + c0.x, q0.y + c1.x);
            *p1 = make_float2(q1.x + c0.y, q1.y + c1.y);
        }
    }
    __syncthreads();

    {   // final: thread t sums 8 split-partials for output element t (r=t>>6, d=t&63)
        float rsum = red[t] + red[512 + t] + red[1024 + t] + red[1536 + t]
                   + red[2048 + t] + red[2560 + t] + red[3072 + t] + red[3584 + t];
        out[(b * 512 + n0 + (t >> 6)) * 64 + (t & 63)] = rsum;
    }
}

extern "C" void kernel_launch(void* const* d_in, const int* in_sizes, int n_in,
                              void* d_out, int out_size) {
    const float* Q  = (const float*)d_in[0];
    const float* K  = (const float*)d_in[1];
    const float* V  = (const float*)d_in[2];
    const float* W1 = (const float*)d_in[3];
    const float* b1 = (const float*)d_in[4];
    const float* W2 = (const float*)d_in[5];
    // b2 cancels in softmax

    float* out = (float*)d_out;                   // B*N*D
    float* att = (float*)d_out + BB * NN * DD;    // B*N*KL

    float*  hq;   cudaGetSymbolAddress((void**)&hq,   g_hq);
    float2* hkT2; cudaGetSymbolAddress((void**)&hkT2, g_hkT2);

    kA<<<384, 256>>>(Q, K, W1, b1, hq, hkT2);
    kBC<<<256, 512>>>(hq, hkT2, W2, V, att, out);
}

// round 14
// speedup vs baseline: 1.5722x; 1.5722x over previous
#include <cuda_runtime.h>
#include <cuda_bf16.h>

// MLPAttention: B=4, N=512, KLEN=512, D=64, TAU=4
//   Wq=W1[0::2], Wk=W1[1::2]; hq=Q@Wq+b1; hk=K@Wk
//   res[n,k] = sum_e relu(hq[n,e]+hk[k,e])*W2[e]   (b2 cancels in softmax)
//   packed f32x2 over e-pairs: fadd2 -> scalar FMNMX relu on halves -> ffma2.
//   att = softmax(res/TAU); out = att@V (V loaded once/block, rowpair broadcasts)
// Outputs: out (B*N*D) then att (B*N*K).

#define BB 4
#define NN 512
#define KL 512
#define DD 64

typedef unsigned long long ull;

__device__ float  g_hq[BB * NN * DD];          // [row][e]
__device__ float2 g_hkT2[BB * (DD / 2) * KL];  // [b][ep][k] = {hk[2ep][k], hk[2ep+1][k]}

__device__ __forceinline__ ull pk2(float x, float y) {
    ull r; asm("mov.b64 %0, {%1, %2};" : "=l"(r) : "f"(x), "f"(y)); return r;
}
__device__ __forceinline__ float2 up2(ull u) {
    float2 f; asm("mov.b64 {%0, %1}, %2;" : "=f"(f.x), "=f"(f.y) : "l"(u)); return f;
}
__device__ __forceinline__ ull fadd2(ull a, ull b) {
    ull r; asm("add.rn.f32x2 %0, %1, %2;" : "=l"(r) : "l"(a), "l"(b)); return r;
}
__device__ __forceinline__ ull ffma2(ull a, ull b, ull c) {
    ull r; asm("fma.rn.f32x2 %0, %1, %2, %3;" : "=l"(r) : "l"(a), "l"(b), "l"(c)); return r;
}

// ---------- Kernel A: hq (2 outputs/W1-load) + hkT2 e-paired ----------
// blocks [0,256): hq, 8 rows each. [256,384): hkT2.
__global__ __launch_bounds__(256) void kA(const float* __restrict__ Q,
                                          const float* __restrict__ K,
                                          const float* __restrict__ W1,
                                          const float* __restrict__ b1,
                                          float* __restrict__ hq,
                                          float2* __restrict__ hkT2) {
    int t = threadIdx.x;
    int bid = blockIdx.x;
    if (bid < 256) {
        __shared__ float Qs[8 * 64];
        int r0 = bid * 8;
        Qs[t]       = Q[r0 * 64 + t];
        Qs[t + 256] = Q[r0 * 64 + 256 + t];
        __syncthreads();
        int rl = t >> 6, e = t & 63;          // rows rl and rl+4
        float bv = __ldg(&b1[e]);
        float acc0 = bv, acc1 = bv;
#pragma unroll
        for (int d = 0; d < 64; d++) {
            float wv = __ldg(&W1[d * 128 + e]);            // W1[2d][e], 1 LDG / 2 FMA
            acc0 = fmaf(Qs[rl * 64 + d], wv, acc0);
            acc1 = fmaf(Qs[(rl + 4) * 64 + d], wv, acc1);
        }
        hq[(r0 + rl) * 64 + e]     = acc0;
        hq[(r0 + rl + 4) * 64 + e] = acc1;
    } else {
        __shared__ float Ks[64 * 65];
        __shared__ float Ws[64 * 16];   // [d][eq]
        int id = bid - 256;
        int b  = id >> 5;
        int kt = (id >> 2) & 7;
        int qt = id & 3;
#pragma unroll
        for (int j = 0; j < 16; j++) {
            int idx = t + 256 * j;
            int kk = idx >> 6, d = idx & 63;
            Ks[kk * 65 + d] = K[(b * 512 + kt * 64 + kk) * 64 + d];
        }
#pragma unroll
        for (int j = 0; j < 4; j++) {
            int idx = t + 256 * j;
            int d = idx >> 4, eq = idx & 15;
            Ws[idx] = W1[d * 128 + 64 + qt * 16 + eq];   // W1[2d+1][qt*16+eq]
        }
        __syncthreads();
        int k = t & 63, ei = t >> 6;
        float a0 = 0.f, a1 = 0.f, a2 = 0.f, a3 = 0.f;
#pragma unroll
        for (int d = 0; d < 64; d++) {
            float kv = Ks[k * 65 + d];
            float4 wv = *(const float4*)&Ws[d * 16 + ei * 4];
            a0 = fmaf(kv, wv.x, a0);
            a1 = fmaf(kv, wv.y, a1);
            a2 = fmaf(kv, wv.z, a2);
            a3 = fmaf(kv, wv.w, a3);
        }
        int e0 = qt * 16 + ei * 4;
        int base = b * (32 * 512) + kt * 64 + k;
        hkT2[base + (e0 >> 1) * 512]       = make_float2(a0, a1);
        hkT2[base + ((e0 >> 1) + 1) * 512] = make_float2(a2, a3);
    }
}

// ---------- Kernel BC: res -> softmax -> att, out = att@V ----------
// grid 256 (b x 64 n-tiles of 8 rows), 512 threads, 2 blocks/SM, ~62 regs.
// S (16KB) lifecycle:
//   res [8][512] floats  ->  att2 ull[4 rowpair][512] (interleaved rowpairs)
//   ->  red [8 split][512] floats (2-pass over 16 k-splits)
__global__ __launch_bounds__(512, 2) void kBC(const float* __restrict__ hq,
                                              const float2* __restrict__ hkT2,
                                              const float* __restrict__ W2,
                                              const float* __restrict__ V,
                                              float* __restrict__ att,
                                              float* __restrict__ out) {
    __shared__ __align__(16) float S[4096];
    __shared__ __align__(16) float hq_p[512];   // [ep][row][par]: ep*16 + row*2 + par
    __shared__ ull w2ps[32];                    // {w2[2ep], w2[2ep+1]}

    int b  = blockIdx.x >> 6;
    int n0 = (blockIdx.x & 63) << 3;
    int t  = threadIdx.x;

    {   // stage hq tile (coalesced read, permuted smem write)
        int row = t >> 6, e = t & 63;
        hq_p[(e >> 1) * 16 + row * 2 + (e & 1)] = hq[(b * 512 + n0 + row) * 64 + e];
    }
    if (t < 32) {
        float2 w = *(const float2*)&W2[2 * t];
        w2ps[t] = pk2(w.x, w.y);
    }
    __syncthreads();

    // ---- phase 1: res[8 rows][k=t], packed over e-pairs, hk prefetched 1 iter ahead ----
    // hq_p[ep] spans 16 floats = 4 ulonglong2: hq22[ep*4 + g] = rows {2g, 2g+1}
    const ull* hkb = (const ull*)(hkT2 + b * (32 * 512) + t);
    const ulonglong2* hq22 = (const ulonglong2*)hq_p;

    ull a0=0, a1=0, a2=0, a3=0, a4=0, a5=0, a6=0, a7=0;
    ull hk_cur = hkb[0];                         // prologue load
#pragma unroll 4
    for (int ep = 0; ep < 32; ep++) {
        ull hk_next = (ep < 31) ? hkb[(ep + 1) * 512] : 0ull;  // LDG.64 issued before math
        ull hkp = hk_cur;
        ull w2p = w2ps[ep];
        ulonglong2 h01 = hq22[ep * 4];           // rows 0,1
        ulonglong2 h23 = hq22[ep * 4 + 1];       // rows 2,3
        ulonglong2 h45 = hq22[ep * 4 + 2];       // rows 4,5
        ulonglong2 h67 = hq22[ep * 4 + 3];       // rows 6,7
        // RSTEP: fadd2 (fma) -> 2x FMNMX relu (alu) -> ffma2 (fma). 4 slots / 2 MACs.
#define RSTEP(A, H) { float2 s2 = up2(fadd2((H), hkp)); \
                      (A) = ffma2(pk2(fmaxf(s2.x, 0.f), fmaxf(s2.y, 0.f)), w2p, (A)); }
        RSTEP(a0, h01.x) RSTEP(a1, h01.y)
        RSTEP(a2, h23.x) RSTEP(a3, h23.y)
        RSTEP(a4, h45.x) RSTEP(a5, h45.y)
        RSTEP(a6, h67.x) RSTEP(a7, h67.y)
#undef RSTEP
        hk_cur = hk_next;
    }
    {   // horizontal add (even-e + odd-e), stage res[8][512]
        float2 x;
        x = up2(a0); S[0 * 512 + t] = x.x + x.y;
        x = up2(a1); S[1 * 512 + t] = x.x + x.y;
        x = up2(a2); S[2 * 512 + t] = x.x + x.y;
        x = up2(a3); S[3 * 512 + t] = x.x + x.y;
        x = up2(a4); S[4 * 512 + t] = x.x + x.y;
        x = up2(a5); S[5 * 512 + t] = x.x + x.y;
        x = up2(a6); S[6 * 512 + t] = x.x + x.y;
        x = up2(a7); S[7 * 512 + t] = x.x + x.y;
    }
    __syncthreads();

    // ---- phase 2: softmax, 16 warps = 2 per row (256 k each) ----
    int w = t >> 5, lane = t & 31;
    int srow = w >> 1, half = w & 1;
    float* pm = hq_p;          // hq_p free now
    float* ps = hq_p + 16;
    float v[8];
    float m = -1e30f;
    {
        const float* rs = S + srow * 512 + half * 256;
#pragma unroll
        for (int i = 0; i < 8; i++) {
            v[i] = rs[lane + 32 * i];
            m = fmaxf(m, v[i]);
        }
    }
#pragma unroll
    for (int o = 16; o; o >>= 1) m = fmaxf(m, __shfl_xor_sync(0xffffffffu, m, o));
    float sum = 0.f;
#pragma unroll
    for (int i = 0; i < 8; i++) {
        v[i] = __expf((v[i] - m) * 0.25f);   // /TAU
        sum += v[i];
    }
#pragma unroll
    for (int o = 16; o; o >>= 1) sum += __shfl_xor_sync(0xffffffffu, sum, o);
    if (lane == 0) { pm[w] = m; ps[w] = sum; }
    __syncthreads();   // publishes pm/ps; closes all res reads

    float scale;
    {
        float m_o = pm[w ^ 1], s_o = ps[w ^ 1];
        float M = fmaxf(m, m_o);
        float f = __expf((m - M) * 0.25f);
        float sum_t = sum * f + s_o * __expf((m_o - M) * 0.25f);
        scale = f / sum_t;
    }
    {   // write att: gmem (coalesced) + S interleaved rowpair:
        // att2 ull[r2][k] at float idx r2*1024 + 2k + par  (par = srow&1)
        float* ap = att + (b * 512 + n0 + srow) * 512 + half * 256 + lane;
        int base = (srow >> 1) * 1024 + (srow & 1) + 2 * (half * 256 + lane);
#pragma unroll
        for (int i = 0; i < 8; i++) {
            float av = v[i] * scale;
            ap[32 * i] = av;
            S[base + 64 * i] = av;
        }
    }
    __syncthreads();

    // ---- phase 3: out = att @ V. 16 warps = 16 k-splits of 32.
    // Thread (s = warp, d2 = lane) covers ALL 8 rows: V loaded once per block.
    int s = w, d2 = lane;
    const float2* Vb = (const float2*)V + ((size_t)(b * 512) + s * 32) * 32 + d2;
    const ull* A2 = (const ull*)S;               // [r2][512]
    ull o0=0, o1=0, o2=0, o3=0, o4=0, o5=0, o6=0, o7=0;  // [r2]x{vx,vy}
#pragma unroll 8
    for (int i = 0; i < 32; i++) {
        int k = s * 32 + i;
        float2 vv = __ldg(Vb + i * 32);          // coalesced LDG.64, 1 load per V elem
        ull vx = pk2(vv.x, vv.x);
        ull vy = pk2(vv.y, vv.y);
        ull q0 = A2[k];                          // broadcast LDS.64: rows {0,1}
        ull q1 = A2[512 + k];                    // rows {2,3}
        ull q2 = A2[1024 + k];                   // rows {4,5}
        ull q3 = A2[1536 + k];                   // rows {6,7}
        o0 = ffma2(q0, vx, o0);  o1 = ffma2(q0, vy, o1);
        o2 = ffma2(q1, vx, o2);  o3 = ffma2(q1, vy, o3);
        o4 = ffma2(q2, vx, o4);  o5 = ffma2(q2, vy, o5);
        o6 = ffma2(q3, vx, o6);  o7 = ffma2(q3, vy, o7);
    }
    __syncthreads();   // att2 reads done -> S becomes red[8][512]

    // 2-pass split reduction: splits 0..7 write, splits 8..15 accumulate.
    float* red = S;
    if (s < 8) {
#pragma unroll
        for (int r2 = 0; r2 < 4; r2++) {
            float2 c0 = up2(r2 == 0 ? o0 : r2 == 1 ? o2 : r2 == 2 ? o4 : o6);
            float2 c1 = up2(r2 == 0 ? o1 : r2 == 1 ? o3 : r2 == 2 ? o5 : o7);
            *(float2*)&red[s * 512 + (2 * r2) * 64 + 2 * d2]     = make_float2(c0.x, c1.x);
            *(float2*)&red[s * 512 + (2 * r2 + 1) * 64 + 2 * d2] = make_float2(c0.y, c1.y);
        }
    }
    __syncthreads();
    if (s >= 8) {
#pragma unroll
        for (int r2 = 0; r2 < 4; r2++) {
            float2 c0 = up2(r2 == 0 ? o0 : r2 == 1 ? o2 : r2 == 2 ? o4 : o6);
            float2 c1 = up2(r2 == 0 ? o1 : r2 == 1 ? o3 : r2 == 2 ? o5 : o7);
            float2* p0 = (float2*)&red[(s - 8) * 512 + (2 * r2) * 64 + 2 * d2];
            float2* p1 = (float2*)&red[(s - 8) * 512 + (2 * r2 + 1) * 64 + 2 * d2];
            float2 q0 = *p0, q1 = *p1;
            *p0 = make_float2(q0.x + c0.x, q0.y + c1.x);
            *p1 = make_float2(q1.x + c0.y, q1.y + c1.y);
        }
    }
    __syncthreads();

    {   // final: thread t sums 8 split-partials for output element t (r=t>>6, d=t&63)
        float rsum = red[t] + red[512 + t] + red[1024 + t] + red[1536 + t]
                   + red[2048 + t] + red[2560 + t] + red[3072 + t] + red[3584 + t];
        out[(b * 512 + n0 + (t >> 6)) * 64 + (t & 63)] = rsum;
    }
}

extern "C" void kernel_launch(void* const* d_in, const int* in_sizes, int n_in,
                              void* d_out, int out_size) {
    const float* Q  = (const float*)d_in[0];
    const float* K  = (const float*)d_in[1];
    const float* V  = (const float*)d_in[2];
    const float* W1 = (const float*)d_in[3];
    const float* b1 = (const float*)d_in[4];
    const float* W2 = (const float*)d_in[5];
    // b2 cancels in softmax

    float* out = (float*)d_out;                   // B*N*D
    float* att = (float*)d_out + BB * NN * DD;    // B*N*KL

    float*  hq;   cudaGetSymbolAddress((void**)&hq,   g_hq);
    float2* hkT2; cudaGetSymbolAddress((void**)&hkT2, g_hkT2);

    kA<<<384, 256>>>(Q, K, W1, b1, hq, hkT2);
    kBC<<<256, 512>>>(hq, hkT2, W2, V, att, out);
}